// round 1
// baseline (speedup 1.0000x reference)
#include <cuda_runtime.h>

#define NN 40000
#define NE 640000
#define NG 2048
#define D  128
#define D2 256
#define NT 10
#define NL 5

// ---------------- scratch (device globals: allocation-free) ----------------
__device__ float g_x[NN * D];       // current node features
__device__ float g_agg[NN * D];     // scatter-add aggregation
__device__ float g_y1[NN * D2];     // hidden after first linear+BN+ReLU
__device__ float g_pool[NG * D];    // per-graph sums
__device__ float g_cnt[NG];         // per-graph node counts

__device__ __forceinline__ void red_add_v4(float* p, float a, float b, float c, float d) {
    asm volatile("red.global.add.v4.f32 [%0], {%1,%2,%3,%4};"
                 :: "l"(p), "f"(a), "f"(b), "f"(c), "f"(d) : "memory");
}

// ---------------- zero kernels ----------------
__global__ void zero_agg_kernel() {
    int i = blockIdx.x * blockDim.x + threadIdx.x;
    if (i < NN * D / 4) ((float4*)g_agg)[i] = make_float4(0.f, 0.f, 0.f, 0.f);
}
__global__ void zero_pool_kernel() {
    int i = blockIdx.x * blockDim.x + threadIdx.x;
    if (i < NG * D) g_pool[i] = 0.f;
    if (i < NG) g_cnt[i] = 0.f;
}

// ---------------- atom encoder: x[n,:] = sum_f atom_emb[f, x_atom[n,f], :] ----------------
__global__ void atom_encode_kernel(const int* __restrict__ x_atom,
                                   const float* __restrict__ atom_emb) {
    int n = blockIdx.x * (blockDim.x >> 5) + (threadIdx.x >> 5);
    int lane = threadIdx.x & 31;
    if (n >= NN) return;
    float4 acc = make_float4(0.f, 0.f, 0.f, 0.f);
#pragma unroll
    for (int f = 0; f < 9; f++) {
        int idx = __ldg(&x_atom[n * 9 + f]);
        float4 v = *(const float4*)&atom_emb[(f * 64 + idx) * D + lane * 4];
        acc.x += v.x; acc.y += v.y; acc.z += v.z; acc.w += v.w;
    }
    *(float4*)&g_x[n * D + lane * 4] = acc;
}

// ---------------- edge kernel: fused bond-emb + relu(x[src]+e) + scatter-add ----------------
__global__ void edge_kernel(const int* __restrict__ ei, const int* __restrict__ ea,
                            const float* __restrict__ bond) {
    int e = blockIdx.x * (blockDim.x >> 5) + (threadIdx.x >> 5);
    int lane = threadIdx.x & 31;
    if (e >= NE) return;
    int src = ei[e], dst = ei[NE + e];
    int a0 = ea[e * 3 + 0], a1 = ea[e * 3 + 1], a2 = ea[e * 3 + 2];
    int off = lane * 4;
    float4 b0 = *(const float4*)&bond[(0 * 8 + a0) * D + off];
    float4 b1 = *(const float4*)&bond[(1 * 8 + a1) * D + off];
    float4 b2 = *(const float4*)&bond[(2 * 8 + a2) * D + off];
    float4 xv = *(const float4*)&g_x[src * D + off];
    float mx = fmaxf(xv.x + b0.x + b1.x + b2.x, 0.f);
    float my = fmaxf(xv.y + b0.y + b1.y + b2.y, 0.f);
    float mz = fmaxf(xv.z + b0.z + b1.z + b2.z, 0.f);
    float mw = fmaxf(xv.w + b0.w + b1.w + b2.w, 0.f);
    red_add_v4(&g_agg[dst * D + off], mx, my, mz, mw);
}

// ---------------- fused GEMM + BN (+ReLU) ----------------
// FUSE=true : A[n,k] = (1+eps)*g_x + g_agg, C = g_y1  (KD=128, NC=256)
// FUSE=false: A = g_y1,                      C = g_x   (KD=256, NC=128)
template<int KD, int NC, bool FUSE, bool DO_RELU>
__global__ __launch_bounds__(256)
void gemm_bn_kernel(const float* __restrict__ epsp,
                    const float* __restrict__ W,
                    const float* __restrict__ bb, const float* __restrict__ gg,
                    const float* __restrict__ btv, const float* __restrict__ mm,
                    const float* __restrict__ vv) {
    constexpr int BM = 64, BN = 128, BK = 32;
    __shared__ float As[BK][BM + 4];
    __shared__ float Bs[BK][BN];
    const float* __restrict__ A = FUSE ? g_x : g_y1;
    float* __restrict__ C = FUSE ? g_y1 : g_x;

    int tid  = threadIdx.x;
    int row0 = blockIdx.y * BM;
    int col0 = blockIdx.x * BN;
    float alpha = FUSE ? (1.f + *epsp) : 1.f;

    int tx = tid & 15, ty = tid >> 4;     // 16x16 thread grid; each thread: 4 rows x 8 cols
    int lr = tid >> 3;                    // A-load row 0..31
    int lc4 = tid & 7;                    // A-load float4 col 0..7

    float acc[4][8];
#pragma unroll
    for (int r = 0; r < 4; r++)
#pragma unroll
        for (int c = 0; c < 8; c++) acc[r][c] = 0.f;

    for (int k0 = 0; k0 < KD; k0 += BK) {
        // A tile 64x32 (transposed into smem)
#pragma unroll
        for (int s = 0; s < 2; s++) {
            int rr = lr + s * 32;
            float4 v = *(const float4*)&A[(row0 + rr) * KD + k0 + lc4 * 4];
            if (FUSE) {
                float4 ag = *(const float4*)&g_agg[(row0 + rr) * KD + k0 + lc4 * 4];
                v.x = alpha * v.x + ag.x; v.y = alpha * v.y + ag.y;
                v.z = alpha * v.z + ag.z; v.w = alpha * v.w + ag.w;
            }
            As[lc4 * 4 + 0][rr] = v.x; As[lc4 * 4 + 1][rr] = v.y;
            As[lc4 * 4 + 2][rr] = v.z; As[lc4 * 4 + 3][rr] = v.w;
        }
        // B tile 32x128 (direct copy)
#pragma unroll
        for (int s = 0; s < 4; s++) {
            int i4 = tid + s * 256;
            int r = i4 >> 5, c4 = i4 & 31;
            *(float4*)&Bs[r][c4 * 4] = *(const float4*)&W[(k0 + r) * NC + col0 + c4 * 4];
        }
        __syncthreads();
#pragma unroll
        for (int kk = 0; kk < BK; kk++) {
            float a[4];
#pragma unroll
            for (int r = 0; r < 4; r++) a[r] = As[kk][ty * 4 + r];
            float4 bq0 = *(const float4*)&Bs[kk][tx * 8];
            float4 bq1 = *(const float4*)&Bs[kk][tx * 8 + 4];
            float b[8] = {bq0.x, bq0.y, bq0.z, bq0.w, bq1.x, bq1.y, bq1.z, bq1.w};
#pragma unroll
            for (int r = 0; r < 4; r++)
#pragma unroll
                for (int c = 0; c < 8; c++) acc[r][c] = fmaf(a[r], b[c], acc[r][c]);
        }
        __syncthreads();
    }

    // epilogue: BN folded to per-column scale/shift, optional ReLU
    float sj[8], tj[8];
#pragma unroll
    for (int c = 0; c < 8; c++) {
        int j = col0 + tx * 8 + c;
        float s = gg[j] * rsqrtf(vv[j] + 1e-5f);
        sj[c] = s;
        tj[c] = (bb[j] - mm[j]) * s + btv[j];
    }
#pragma unroll
    for (int r = 0; r < 4; r++) {
        int n = row0 + ty * 4 + r;
        float o[8];
#pragma unroll
        for (int c = 0; c < 8; c++) {
            float z = acc[r][c] * sj[c] + tj[c];
            o[c] = DO_RELU ? fmaxf(z, 0.f) : z;
        }
        *(float4*)&C[n * NC + col0 + tx * 8]     = make_float4(o[0], o[1], o[2], o[3]);
        *(float4*)&C[n * NC + col0 + tx * 8 + 4] = make_float4(o[4], o[5], o[6], o[7]);
    }
}

// ---------------- global mean pool (sums + counts) ----------------
__global__ void pool_kernel(const int* __restrict__ batch) {
    int n = blockIdx.x * (blockDim.x >> 5) + (threadIdx.x >> 5);
    int lane = threadIdx.x & 31;
    if (n >= NN) return;
    int g = batch[n];
    float4 v = *(const float4*)&g_x[n * D + lane * 4];
    red_add_v4(&g_pool[g * D + lane * 4], v.x, v.y, v.z, v.w);
    if (lane == 0) atomicAdd(&g_cnt[g], 1.0f);
}

// ---------------- prediction head ----------------
__global__ void head_kernel(const float* __restrict__ Wp, const float* __restrict__ bp,
                            float* __restrict__ out) {
    int id = blockIdx.x * blockDim.x + threadIdx.x;
    if (id >= NG * NT) return;
    int g = id / NT, t = id % NT;
    float inv = 1.f / fmaxf(g_cnt[g], 1.f);
    float acc = bp[t];
#pragma unroll 8
    for (int d = 0; d < D; d++)
        acc = fmaf(g_pool[g * D + d] * inv, Wp[d * NT + t], acc);
    out[id] = acc;
}

// ---------------- launch ----------------
extern "C" void kernel_launch(void* const* d_in, const int* in_sizes, int n_in,
                              void* d_out, int out_size) {
    const int*   x_atom  = (const int*)d_in[0];
    const int*   ei      = (const int*)d_in[1];
    const int*   ea      = (const int*)d_in[2];
    const int*   batch   = (const int*)d_in[3];
    const float* atom_emb= (const float*)d_in[4];
    const float* bond_emb= (const float*)d_in[5];
    const float* eps     = (const float*)d_in[6];
    const float* W1      = (const float*)d_in[7];
    const float* b1      = (const float*)d_in[8];
    const float* g1      = (const float*)d_in[9];
    const float* bt1     = (const float*)d_in[10];
    const float* m1      = (const float*)d_in[11];
    const float* v1      = (const float*)d_in[12];
    const float* W2      = (const float*)d_in[13];
    const float* b2      = (const float*)d_in[14];
    const float* gO      = (const float*)d_in[15];
    const float* btO     = (const float*)d_in[16];
    const float* mO      = (const float*)d_in[17];
    const float* vO      = (const float*)d_in[18];
    const float* Wp      = (const float*)d_in[19];
    const float* bp      = (const float*)d_in[20];
    float* out = (float*)d_out;

    atom_encode_kernel<<<NN / 8, 256>>>(x_atom, atom_emb);

    for (int i = 0; i < NL; i++) {
        zero_agg_kernel<<<(NN * D / 4 + 255) / 256, 256>>>();
        edge_kernel<<<NE / 8, 256>>>(ei, ea, bond_emb + i * 3 * 8 * D);
        gemm_bn_kernel<128, 256, true, true><<<dim3(2, NN / 64), 256>>>(
            eps + i, W1 + i * 128 * 256,
            b1 + i * 256, g1 + i * 256, bt1 + i * 256, m1 + i * 256, v1 + i * 256);
        if (i < NL - 1) {
            gemm_bn_kernel<256, 128, false, true><<<dim3(1, NN / 64), 256>>>(
                eps + i, W2 + i * 256 * 128,
                b2 + i * 128, gO + i * 128, btO + i * 128, mO + i * 128, vO + i * 128);
        } else {
            gemm_bn_kernel<256, 128, false, false><<<dim3(1, NN / 64), 256>>>(
                eps + i, W2 + i * 256 * 128,
                b2 + i * 128, gO + i * 128, btO + i * 128, mO + i * 128, vO + i * 128);
        }
    }

    zero_pool_kernel<<<(NG * D + 255) / 256, 256>>>();
    pool_kernel<<<NN / 8, 256>>>(batch);
    head_kernel<<<(NG * NT + 255) / 256, 256>>>(Wp, bp, out);
}

// round 5
// speedup vs baseline: 1.4889x; 1.4889x over previous
#include <cuda_runtime.h>
#include <cuda_bf16.h>
#include <cstdint>

#define NN 40000
#define NE 640000
#define NG 2048
#define D  128
#define NT 10
#define NL 5

// ---------------- scratch (device globals: allocation-free) ----------------
__device__ float g_x[NN * D];                 // current node features (fp32)
__device__ float g_agg[NN * D];               // scatter-add aggregation
__device__ __align__(16) __nv_bfloat16 g_A1[NN * 384];          // [hi|lo|hi] of (1+eps)x+agg
__device__ __align__(16) __nv_bfloat16 g_A2[(size_t)NN * 768];  // [hi|lo|hi] of MLP hidden
__device__ __align__(16) __nv_bfloat16 g_W1T[NL * 256 * 384];   // [n][k'] per layer
__device__ __align__(16) __nv_bfloat16 g_W2T[NL * 128 * 768];
__device__ float g_pool[NG * D];
__device__ float g_cnt[NG];

__device__ __forceinline__ void red_add_v4(float* p, float a, float b, float c, float d) {
    asm volatile("red.global.add.v4.f32 [%0], {%1,%2,%3,%4};"
                 :: "l"(p), "f"(a), "f"(b), "f"(c), "f"(d) : "memory");
}
__device__ __forceinline__ void cp16(uint32_t s, const void* g) {
    asm volatile("cp.async.cg.shared.global [%0], [%1], 16;" :: "r"(s), "l"(g));
}
__device__ __forceinline__ void ldsm_x4(uint32_t& r0, uint32_t& r1, uint32_t& r2, uint32_t& r3,
                                        uint32_t addr) {
    asm volatile("ldmatrix.sync.aligned.m8n8.x4.shared.b16 {%0,%1,%2,%3}, [%4];"
                 : "=r"(r0), "=r"(r1), "=r"(r2), "=r"(r3) : "r"(addr));
}
__device__ __forceinline__ void mma16816(float* d, const uint32_t* a, uint32_t b0, uint32_t b1) {
    asm volatile("mma.sync.aligned.m16n8k16.row.col.f32.bf16.bf16.f32 "
                 "{%0,%1,%2,%3},{%4,%5,%6,%7},{%8,%9},{%0,%1,%2,%3};"
                 : "+f"(d[0]), "+f"(d[1]), "+f"(d[2]), "+f"(d[3])
                 : "r"(a[0]), "r"(a[1]), "r"(a[2]), "r"(a[3]), "r"(b0), "r"(b1));
}

// ---------------- zero kernels ----------------
__global__ void zero_agg_kernel() {
    int i = blockIdx.x * blockDim.x + threadIdx.x;
    if (i < NN * D / 4) ((float4*)g_agg)[i] = make_float4(0.f, 0.f, 0.f, 0.f);
}
__global__ void zero_pool_kernel() {
    int i = blockIdx.x * blockDim.x + threadIdx.x;
    if (i < NG * D) g_pool[i] = 0.f;
    if (i < NG) g_cnt[i] = 0.f;
}

// ---------------- atom encoder ----------------
__global__ void atom_encode_kernel(const int* __restrict__ x_atom,
                                   const float* __restrict__ atom_emb) {
    int n = blockIdx.x * (blockDim.x >> 5) + (threadIdx.x >> 5);
    int lane = threadIdx.x & 31;
    if (n >= NN) return;
    float4 acc = make_float4(0.f, 0.f, 0.f, 0.f);
#pragma unroll
    for (int f = 0; f < 9; f++) {
        int idx = __ldg(&x_atom[n * 9 + f]);
        float4 v = *(const float4*)&atom_emb[(f * 64 + idx) * D + lane * 4];
        acc.x += v.x; acc.y += v.y; acc.z += v.z; acc.w += v.w;
    }
    *(float4*)&g_x[n * D + lane * 4] = acc;
}

// ---------------- edge kernel: fused bond-emb + relu(x[src]+e) + scatter-add ----------------
__global__ void edge_kernel(const int* __restrict__ ei, const int* __restrict__ ea,
                            const float* __restrict__ bond) {
    int e = blockIdx.x * (blockDim.x >> 5) + (threadIdx.x >> 5);
    int lane = threadIdx.x & 31;
    if (e >= NE) return;
    int src = ei[e], dst = ei[NE + e];
    int a0 = ea[e * 3 + 0], a1 = ea[e * 3 + 1], a2 = ea[e * 3 + 2];
    int off = lane * 4;
    float4 b0 = *(const float4*)&bond[(0 * 8 + a0) * D + off];
    float4 b1 = *(const float4*)&bond[(1 * 8 + a1) * D + off];
    float4 b2 = *(const float4*)&bond[(2 * 8 + a2) * D + off];
    float4 xv = *(const float4*)&g_x[src * D + off];
    float mx = fmaxf(xv.x + b0.x + b1.x + b2.x, 0.f);
    float my = fmaxf(xv.y + b0.y + b1.y + b2.y, 0.f);
    float mz = fmaxf(xv.z + b0.z + b1.z + b2.z, 0.f);
    float mw = fmaxf(xv.w + b0.w + b1.w + b2.w, 0.f);
    red_add_v4(&g_agg[dst * D + off], mx, my, mz, mw);
}

// ---------------- weight split prep (all layers, both GEMMs) ----------------
__global__ void prep_w_kernel(const float* __restrict__ W1, const float* __restrict__ W2) {
    int idx = blockIdx.x * blockDim.x + threadIdx.x;
    if (idx >= NL * 196608) return;
    int layer = idx / 196608, rem = idx % 196608;
    if (rem < 98304) {  // W1T: n in [0,256), kp in [0,384)
        int n = rem / 384, kp = rem % 384;
        int kb = kp >> 7, k = kp & 127;
        float w = W1[layer * 32768 + k * 256 + n];
        __nv_bfloat16 h = __float2bfloat16(w);
        g_W1T[layer * 98304 + rem] =
            (kb < 2) ? h : __float2bfloat16(w - __bfloat162float(h));
    } else {            // W2T: n in [0,128), kp in [0,768)
        int r2 = rem - 98304;
        int n = r2 / 768, kp = r2 % 768;
        int kb = kp >> 8, k = kp & 255;
        float w = W2[layer * 32768 + k * 128 + n];
        __nv_bfloat16 h = __float2bfloat16(w);
        g_W2T[layer * 98304 + r2] =
            (kb < 2) ? h : __float2bfloat16(w - __bfloat162float(h));
    }
}

// ---------------- A1 split prep: (1+eps)x+agg -> [hi|lo|hi] bf16 ----------------
__global__ void prep_a1_kernel(const float* __restrict__ epsp) {
    int n = blockIdx.x * (blockDim.x >> 5) + (threadIdx.x >> 5);
    int lane = threadIdx.x & 31;
    if (n >= NN) return;
    float alpha = 1.f + *epsp;
    float4 xv = *(const float4*)&g_x[n * D + lane * 4];
    float4 av = *(const float4*)&g_agg[n * D + lane * 4];
    float a0 = alpha * xv.x + av.x, a1 = alpha * xv.y + av.y;
    float a2 = alpha * xv.z + av.z, a3 = alpha * xv.w + av.w;
    __nv_bfloat16 h0 = __float2bfloat16(a0), h1 = __float2bfloat16(a1);
    __nv_bfloat16 h2 = __float2bfloat16(a2), h3 = __float2bfloat16(a3);
    __nv_bfloat162 hp0, hp1, lp0, lp1;
    hp0.x = h0; hp0.y = h1; hp1.x = h2; hp1.y = h3;
    lp0.x = __float2bfloat16(a0 - __bfloat162float(h0));
    lp0.y = __float2bfloat16(a1 - __bfloat162float(h1));
    lp1.x = __float2bfloat16(a2 - __bfloat162float(h2));
    lp1.y = __float2bfloat16(a3 - __bfloat162float(h3));
    __nv_bfloat16* base = &g_A1[n * 384 + lane * 4];
    *(__nv_bfloat162*)(base + 0)   = hp0; *(__nv_bfloat162*)(base + 2)   = hp1;
    *(__nv_bfloat162*)(base + 128) = lp0; *(__nv_bfloat162*)(base + 130) = lp1;
    *(__nv_bfloat162*)(base + 256) = hp0; *(__nv_bfloat162*)(base + 258) = hp1;
}

// ---------------- tensor-core GEMM + BN epilogue ----------------
// WHICH 0 (GEMM1): A=g_A1 [NN x 384], B=g_W1T layer slice, relu -> bf16 split to g_A2
// WHICH 1 (GEMM2): A=g_A2 [NN x 768], B=g_W2T layer slice, outer BN (+relu) -> fp32 g_x
template<int WHICH, bool RELU>
__global__ __launch_bounds__(256)
void mma_gemm_kernel(int wOff,
                     const float* __restrict__ bb, const float* __restrict__ gg,
                     const float* __restrict__ btv, const float* __restrict__ mm,
                     const float* __restrict__ vv) {
    constexpr int KTOT = (WHICH == 0) ? 384 : 768;
    constexpr int STRIDE = 40;  // padded row stride (bf16) for conflict-free ldmatrix
    constexpr int TILEW  = 128 * STRIDE;
    __shared__ __align__(16) __nv_bfloat16 sA[2][TILEW];
    __shared__ __align__(16) __nv_bfloat16 sB[2][TILEW];

    const __nv_bfloat16* __restrict__ A = (WHICH == 0) ? g_A1 : g_A2;
    const __nv_bfloat16* __restrict__ B = ((WHICH == 0) ? g_W1T : g_W2T) + wOff;

    const int tid = threadIdx.x, wid = tid >> 5, lane = tid & 31;
    const int wm = (wid & 3) * 32, wn = (wid >> 2) * 64;
    const int row0 = blockIdx.y * 128, col0 = blockIdx.x * 128;

    uint32_t aBase = (uint32_t)__cvta_generic_to_shared(&sA[0][0]);
    uint32_t bBase = (uint32_t)__cvta_generic_to_shared(&sB[0][0]);

    float acc[2][8][4];
#pragma unroll
    for (int i = 0; i < 2; i++)
#pragma unroll
        for (int j = 0; j < 8; j++)
#pragma unroll
            for (int k = 0; k < 4; k++) acc[i][j][k] = 0.f;

    const int NSTG = KTOT / 32;
    const int lr = tid >> 2, lc = tid & 3;

    auto load_stage = [&](int s) {
        int buf = s & 1, k0 = s * 32;
#pragma unroll
        for (int q0 = 0; q0 < 2; q0++) {
            int r = lr + q0 * 64;
            int row = row0 + r; if (row >= NN) row = NN - 1;
            cp16(aBase + (uint32_t)(buf * TILEW + r * STRIDE + lc * 8) * 2,
                 A + (size_t)row * KTOT + k0 + lc * 8);
        }
#pragma unroll
        for (int q0 = 0; q0 < 2; q0++) {
            int r = lr + q0 * 64;
            cp16(bBase + (uint32_t)(buf * TILEW + r * STRIDE + lc * 8) * 2,
                 B + (size_t)(col0 + r) * KTOT + k0 + lc * 8);
        }
    };

    load_stage(0);
    asm volatile("cp.async.commit_group;");

    for (int s = 0; s < NSTG; s++) {
        if (s + 1 < NSTG) {
            load_stage(s + 1);
            asm volatile("cp.async.commit_group;");
            asm volatile("cp.async.wait_group 1;");
        } else {
            asm volatile("cp.async.wait_group 0;");
        }
        __syncthreads();

        int buf = s & 1;
#pragma unroll
        for (int kk = 0; kk < 32; kk += 16) {
            uint32_t a[2][4], b[4][4];
#pragma unroll
            for (int mt = 0; mt < 2; mt++) {
                uint32_t addr = aBase +
                    (uint32_t)(buf * TILEW + (wm + mt * 16 + (lane & 15)) * STRIDE +
                               kk + (lane >> 4) * 8) * 2;
                ldsm_x4(a[mt][0], a[mt][1], a[mt][2], a[mt][3], addr);
            }
#pragma unroll
            for (int nb = 0; nb < 4; nb++) {
                uint32_t addr = bBase +
                    (uint32_t)(buf * TILEW + (wn + nb * 16 + (lane & 15)) * STRIDE +
                               kk + (lane >> 4) * 8) * 2;
                ldsm_x4(b[nb][0], b[nb][1], b[nb][2], b[nb][3], addr);
            }
#pragma unroll
            for (int mt = 0; mt < 2; mt++)
#pragma unroll
                for (int nt = 0; nt < 8; nt++) {
                    int nb = nt >> 1, sel = nt & 1;
                    uint32_t b0 = sel ? b[nb][1] : b[nb][0];
                    uint32_t b1 = sel ? b[nb][3] : b[nb][2];
                    mma16816(acc[mt][nt], a[mt], b0, b1);
                }
        }
        __syncthreads();
    }

    // epilogue: folded BN, optional ReLU; GEMM1 additionally emits bf16 split
    const int r = lane >> 2, c2 = (lane & 3) * 2;
#pragma unroll
    for (int nt = 0; nt < 8; nt++) {
        int j = col0 + wn + nt * 8 + c2;
        float s0 = gg[j] * rsqrtf(vv[j] + 1e-5f);
        float t0 = (bb[j] - mm[j]) * s0 + btv[j];
        float s1 = gg[j + 1] * rsqrtf(vv[j + 1] + 1e-5f);
        float t1 = (bb[j + 1] - mm[j + 1]) * s1 + btv[j + 1];
#pragma unroll
        for (int mt = 0; mt < 2; mt++)
#pragma unroll
            for (int h = 0; h < 2; h++) {
                int row = row0 + wm + mt * 16 + r + h * 8;
                if (row >= NN) continue;
                float z0 = acc[mt][nt][h * 2 + 0] * s0 + t0;
                float z1 = acc[mt][nt][h * 2 + 1] * s1 + t1;
                if (WHICH == 0 || RELU) { z0 = fmaxf(z0, 0.f); z1 = fmaxf(z1, 0.f); }
                if (WHICH == 0) {
                    __nv_bfloat16 h0 = __float2bfloat16(z0), h1 = __float2bfloat16(z1);
                    __nv_bfloat162 hp, lp;
                    hp.x = h0; hp.y = h1;
                    lp.x = __float2bfloat16(z0 - __bfloat162float(h0));
                    lp.y = __float2bfloat16(z1 - __bfloat162float(h1));
                    __nv_bfloat16* base = &g_A2[(size_t)row * 768 + j];
                    *(__nv_bfloat162*)(base + 0)   = hp;
                    *(__nv_bfloat162*)(base + 256) = lp;
                    *(__nv_bfloat162*)(base + 512) = hp;
                } else {
                    *(float2*)&g_x[(size_t)row * D + j] = make_float2(z0, z1);
                }
            }
    }
}

// ---------------- global mean pool ----------------
__global__ void pool_kernel(const int* __restrict__ batch) {
    int n = blockIdx.x * (blockDim.x >> 5) + (threadIdx.x >> 5);
    int lane = threadIdx.x & 31;
    if (n >= NN) return;
    int g = batch[n];
    float4 v = *(const float4*)&g_x[n * D + lane * 4];
    red_add_v4(&g_pool[g * D + lane * 4], v.x, v.y, v.z, v.w);
    if (lane == 0) atomicAdd(&g_cnt[g], 1.0f);
}

// ---------------- prediction head ----------------
__global__ void head_kernel(const float* __restrict__ Wp, const float* __restrict__ bp,
                            float* __restrict__ out) {
    int id = blockIdx.x * blockDim.x + threadIdx.x;
    if (id >= NG * NT) return;
    int g = id / NT, t = id % NT;
    float inv = 1.f / fmaxf(g_cnt[g], 1.f);
    float acc = bp[t];
#pragma unroll 8
    for (int d = 0; d < D; d++)
        acc = fmaf(g_pool[g * D + d] * inv, Wp[d * NT + t], acc);
    out[id] = acc;
}

// ---------------- launch ----------------
extern "C" void kernel_launch(void* const* d_in, const int* in_sizes, int n_in,
                              void* d_out, int out_size) {
    const int*   x_atom  = (const int*)d_in[0];
    const int*   ei      = (const int*)d_in[1];
    const int*   ea      = (const int*)d_in[2];
    const int*   batch   = (const int*)d_in[3];
    const float* atom_emb= (const float*)d_in[4];
    const float* bond_emb= (const float*)d_in[5];
    const float* eps     = (const float*)d_in[6];
    const float* W1      = (const float*)d_in[7];
    const float* b1      = (const float*)d_in[8];
    const float* g1      = (const float*)d_in[9];
    const float* bt1     = (const float*)d_in[10];
    const float* m1      = (const float*)d_in[11];
    const float* v1      = (const float*)d_in[12];
    const float* W2      = (const float*)d_in[13];
    const float* b2      = (const float*)d_in[14];
    const float* gO      = (const float*)d_in[15];
    const float* btO     = (const float*)d_in[16];
    const float* mO      = (const float*)d_in[17];
    const float* vO      = (const float*)d_in[18];
    const float* Wp      = (const float*)d_in[19];
    const float* bp      = (const float*)d_in[20];
    float* out = (float*)d_out;

    prep_w_kernel<<<(NL * 196608 + 255) / 256, 256>>>(W1, W2);
    atom_encode_kernel<<<NN / 8, 256>>>(x_atom, atom_emb);

    const int MT = (NN + 127) / 128;  // 313 row tiles

    for (int i = 0; i < NL; i++) {
        zero_agg_kernel<<<(NN * D / 4 + 255) / 256, 256>>>();
        edge_kernel<<<NE / 8, 256>>>(ei, ea, bond_emb + i * 3 * 8 * D);
        prep_a1_kernel<<<NN / 8, 256>>>(eps + i);

        // GEMM1: [NN x 384] x [384 x 256] -> hidden (relu) -> g_A2 splits
        mma_gemm_kernel<0, true><<<dim3(2, MT), 256>>>(
            i * 98304,
            b1 + i * 256, g1 + i * 256, bt1 + i * 256, m1 + i * 256, v1 + i * 256);

        // GEMM2: [NN x 768] x [768 x 128] -> outer BN (+relu except last) -> g_x
        if (i < NL - 1)
            mma_gemm_kernel<1, true><<<dim3(1, MT), 256>>>(
                i * 98304,
                b2 + i * 128, gO + i * 128, btO + i * 128, mO + i * 128, vO + i * 128);
        else
            mma_gemm_kernel<1, false><<<dim3(1, MT), 256>>>(
                i * 98304,
                b2 + i * 128, gO + i * 128, btO + i * 128, mO + i * 128, vO + i * 128);
    }

    zero_pool_kernel<<<(NG * D + 255) / 256, 256>>>();
    pool_kernel<<<NN / 8, 256>>>(batch);
    head_kernel<<<(NG * NT + 255) / 256, 256>>>(Wp, bp, out);
}

// round 6
// speedup vs baseline: 1.6825x; 1.1300x over previous
#include <cuda_runtime.h>
#include <cuda_bf16.h>
#include <cstdint>

#define NN 40000
#define NE 640000
#define NG 2048
#define D  128
#define NT 10
#define NL 5

// ---------------- scratch (device globals: allocation-free) ----------------
__device__ float g_x[NN * D];                 // current node features (fp32)
__device__ __align__(16) __nv_bfloat16 g_A1[NN * 384];          // [hi|lo|hi] of (1+eps)x+agg
__device__ __align__(16) __nv_bfloat16 g_A2[(size_t)NN * 768];  // [hi|lo|hi] of MLP hidden
__device__ __align__(16) __nv_bfloat16 g_W1T[NL * 256 * 384];   // [n][k'] per layer
__device__ __align__(16) __nv_bfloat16 g_W2T[NL * 128 * 768];
__device__ float g_pool[NG * D];
__device__ float g_cnt[NG];
// CSR scratch (built once per replay)
__device__ int g_deg[NN];
__device__ int g_pos[NN];
__device__ int g_rowptr[NN + 1];
__device__ int g_csr_src[NE];
__device__ int g_csr_code[NE];   // packed bond attrs: a0 | a1<<3 | a2<<6

__device__ __forceinline__ void red_add_v4(float* p, float a, float b, float c, float d) {
    asm volatile("red.global.add.v4.f32 [%0], {%1,%2,%3,%4};"
                 :: "l"(p), "f"(a), "f"(b), "f"(c), "f"(d) : "memory");
}
__device__ __forceinline__ void cp16(uint32_t s, const void* g) {
    asm volatile("cp.async.cg.shared.global [%0], [%1], 16;" :: "r"(s), "l"(g));
}
__device__ __forceinline__ void ldsm_x4(uint32_t& r0, uint32_t& r1, uint32_t& r2, uint32_t& r3,
                                        uint32_t addr) {
    asm volatile("ldmatrix.sync.aligned.m8n8.x4.shared.b16 {%0,%1,%2,%3}, [%4];"
                 : "=r"(r0), "=r"(r1), "=r"(r2), "=r"(r3) : "r"(addr));
}
__device__ __forceinline__ void mma16816(float* d, const uint32_t* a, uint32_t b0, uint32_t b1) {
    asm volatile("mma.sync.aligned.m16n8k16.row.col.f32.bf16.bf16.f32 "
                 "{%0,%1,%2,%3},{%4,%5,%6,%7},{%8,%9},{%0,%1,%2,%3};"
                 : "+f"(d[0]), "+f"(d[1]), "+f"(d[2]), "+f"(d[3])
                 : "r"(a[0]), "r"(a[1]), "r"(a[2]), "r"(a[3]), "r"(b0), "r"(b1));
}

// ---------------- CSR build (once per replay) ----------------
__global__ void zero_deg_kernel() {
    int i = blockIdx.x * blockDim.x + threadIdx.x;
    if (i < NN) { g_deg[i] = 0; g_pos[i] = 0; }
}
__global__ void hist_kernel(const int* __restrict__ ei) {
    int e = blockIdx.x * blockDim.x + threadIdx.x;
    if (e < NE) atomicAdd(&g_deg[ei[NE + e]], 1);
}
__global__ void scan_kernel() {   // single block, 1024 threads
    __shared__ int sh[1024];
    __shared__ int carry;
    int tid = threadIdx.x;
    if (tid == 0) carry = 0;
    __syncthreads();
    for (int base = 0; base < NN; base += 1024) {
        int i = base + tid;
        int v = (i < NN) ? g_deg[i] : 0;
        sh[tid] = v;
        __syncthreads();
#pragma unroll
        for (int off = 1; off < 1024; off <<= 1) {
            int t = (tid >= off) ? sh[tid - off] : 0;
            __syncthreads();
            sh[tid] += t;
            __syncthreads();
        }
        if (i < NN) g_rowptr[i + 1] = carry + sh[tid];
        __syncthreads();
        if (tid == 1023) carry += sh[1023];
        __syncthreads();
    }
    if (tid == 0) g_rowptr[0] = 0;
}
__global__ void permute_kernel(const int* __restrict__ ei, const int* __restrict__ ea) {
    int e = blockIdx.x * blockDim.x + threadIdx.x;
    if (e >= NE) return;
    int dst = ei[NE + e];
    int p = g_rowptr[dst] + atomicAdd(&g_pos[dst], 1);
    g_csr_src[p] = ei[e];
    g_csr_code[p] = ea[e * 3 + 0] | (ea[e * 3 + 1] << 3) | (ea[e * 3 + 2] << 6);
}

// ---------------- zero pool ----------------
__global__ void zero_pool_kernel() {
    int i = blockIdx.x * blockDim.x + threadIdx.x;
    if (i < NG * D) g_pool[i] = 0.f;
    if (i < NG) g_cnt[i] = 0.f;
}

// ---------------- atom encoder ----------------
__global__ void atom_encode_kernel(const int* __restrict__ x_atom,
                                   const float* __restrict__ atom_emb) {
    int n = blockIdx.x * (blockDim.x >> 5) + (threadIdx.x >> 5);
    int lane = threadIdx.x & 31;
    if (n >= NN) return;
    float4 acc = make_float4(0.f, 0.f, 0.f, 0.f);
#pragma unroll
    for (int f = 0; f < 9; f++) {
        int idx = __ldg(&x_atom[n * 9 + f]);
        float4 v = *(const float4*)&atom_emb[(f * 64 + idx) * D + lane * 4];
        acc.x += v.x; acc.y += v.y; acc.z += v.z; acc.w += v.w;
    }
    *(float4*)&g_x[n * D + lane * 4] = acc;
}

// ---------------- fused aggregation + A1-split kernel ----------------
// one warp per dst node: acc = sum_e relu(x[src_e] + bond(code_e)); a = (1+eps)x + acc
// writes bf16 [hi|lo|hi] split directly to g_A1.
__global__ __launch_bounds__(256)
void agg_a1_kernel(const float* __restrict__ epsp, const float* __restrict__ bond) {
    __shared__ float sbond[3 * 8 * D];   // 12 KB
    int tid = threadIdx.x;
    for (int i = tid; i < 3 * 8 * D / 4; i += 256)
        ((float4*)sbond)[i] = ((const float4*)bond)[i];
    __syncthreads();

    int n = blockIdx.x * 8 + (tid >> 5);
    int lane = tid & 31;
    if (n >= NN) return;
    int off = lane * 4;

    float4 acc = make_float4(0.f, 0.f, 0.f, 0.f);
    int e = g_rowptr[n], end = g_rowptr[n + 1];

    auto accum = [&](int src, int code) {
        float4 xv = *(const float4*)&g_x[src * D + off];
        float4 b0 = *(const float4*)&sbond[(code & 7) * D + off];
        float4 b1 = *(const float4*)&sbond[1024 + ((code >> 3) & 7) * D + off];
        float4 b2 = *(const float4*)&sbond[2048 + ((code >> 6) & 7) * D + off];
        acc.x += fmaxf(xv.x + b0.x + b1.x + b2.x, 0.f);
        acc.y += fmaxf(xv.y + b0.y + b1.y + b2.y, 0.f);
        acc.z += fmaxf(xv.z + b0.z + b1.z + b2.z, 0.f);
        acc.w += fmaxf(xv.w + b0.w + b1.w + b2.w, 0.f);
    };

    for (; e + 3 < end; e += 4) {
        int s0 = g_csr_src[e],     c0 = g_csr_code[e];
        int s1 = g_csr_src[e + 1], c1 = g_csr_code[e + 1];
        int s2 = g_csr_src[e + 2], c2 = g_csr_code[e + 2];
        int s3 = g_csr_src[e + 3], c3 = g_csr_code[e + 3];
        accum(s0, c0); accum(s1, c1); accum(s2, c2); accum(s3, c3);
    }
    for (; e < end; e++) accum(g_csr_src[e], g_csr_code[e]);

    float alpha = 1.f + *epsp;
    float4 xn = *(const float4*)&g_x[n * D + off];
    float a0 = alpha * xn.x + acc.x, a1 = alpha * xn.y + acc.y;
    float a2 = alpha * xn.z + acc.z, a3 = alpha * xn.w + acc.w;
    __nv_bfloat16 h0 = __float2bfloat16(a0), h1 = __float2bfloat16(a1);
    __nv_bfloat16 h2 = __float2bfloat16(a2), h3 = __float2bfloat16(a3);
    __nv_bfloat162 hp0, hp1, lp0, lp1;
    hp0.x = h0; hp0.y = h1; hp1.x = h2; hp1.y = h3;
    lp0.x = __float2bfloat16(a0 - __bfloat162float(h0));
    lp0.y = __float2bfloat16(a1 - __bfloat162float(h1));
    lp1.x = __float2bfloat16(a2 - __bfloat162float(h2));
    lp1.y = __float2bfloat16(a3 - __bfloat162float(h3));
    __nv_bfloat16* base = &g_A1[n * 384 + off];
    *(__nv_bfloat162*)(base + 0)   = hp0; *(__nv_bfloat162*)(base + 2)   = hp1;
    *(__nv_bfloat162*)(base + 128) = lp0; *(__nv_bfloat162*)(base + 130) = lp1;
    *(__nv_bfloat162*)(base + 256) = hp0; *(__nv_bfloat162*)(base + 258) = hp1;
}

// ---------------- weight split prep ----------------
__global__ void prep_w_kernel(const float* __restrict__ W1, const float* __restrict__ W2) {
    int idx = blockIdx.x * blockDim.x + threadIdx.x;
    if (idx >= NL * 196608) return;
    int layer = idx / 196608, rem = idx % 196608;
    if (rem < 98304) {  // W1T: n in [0,256), kp in [0,384)
        int n = rem / 384, kp = rem % 384;
        int kb = kp >> 7, k = kp & 127;
        float w = W1[layer * 32768 + k * 256 + n];
        __nv_bfloat16 h = __float2bfloat16(w);
        g_W1T[layer * 98304 + rem] =
            (kb < 2) ? h : __float2bfloat16(w - __bfloat162float(h));
    } else {            // W2T: n in [0,128), kp in [0,768)
        int r2 = rem - 98304;
        int n = r2 / 768, kp = r2 % 768;
        int kb = kp >> 8, k = kp & 255;
        float w = W2[layer * 32768 + k * 128 + n];
        __nv_bfloat16 h = __float2bfloat16(w);
        g_W2T[layer * 98304 + r2] =
            (kb < 2) ? h : __float2bfloat16(w - __bfloat162float(h));
    }
}

// ---------------- tensor-core GEMM + BN epilogue ----------------
template<int WHICH, bool RELU>
__global__ __launch_bounds__(256)
void mma_gemm_kernel(int wOff,
                     const float* __restrict__ bb, const float* __restrict__ gg,
                     const float* __restrict__ btv, const float* __restrict__ mm,
                     const float* __restrict__ vv) {
    constexpr int KTOT = (WHICH == 0) ? 384 : 768;
    constexpr int STRIDE = 40;
    constexpr int TILEW  = 128 * STRIDE;
    __shared__ __align__(16) __nv_bfloat16 sA[2][TILEW];
    __shared__ __align__(16) __nv_bfloat16 sB[2][TILEW];

    const __nv_bfloat16* __restrict__ A = (WHICH == 0) ? g_A1 : g_A2;
    const __nv_bfloat16* __restrict__ B = ((WHICH == 0) ? g_W1T : g_W2T) + wOff;

    const int tid = threadIdx.x, wid = tid >> 5, lane = tid & 31;
    const int wm = (wid & 3) * 32, wn = (wid >> 2) * 64;
    const int row0 = blockIdx.y * 128, col0 = blockIdx.x * 128;

    uint32_t aBase = (uint32_t)__cvta_generic_to_shared(&sA[0][0]);
    uint32_t bBase = (uint32_t)__cvta_generic_to_shared(&sB[0][0]);

    float acc[2][8][4];
#pragma unroll
    for (int i = 0; i < 2; i++)
#pragma unroll
        for (int j = 0; j < 8; j++)
#pragma unroll
            for (int k = 0; k < 4; k++) acc[i][j][k] = 0.f;

    const int NSTG = KTOT / 32;
    const int lr = tid >> 2, lc = tid & 3;

    auto load_stage = [&](int s) {
        int buf = s & 1, k0 = s * 32;
#pragma unroll
        for (int q0 = 0; q0 < 2; q0++) {
            int r = lr + q0 * 64;
            int row = row0 + r; if (row >= NN) row = NN - 1;
            cp16(aBase + (uint32_t)(buf * TILEW + r * STRIDE + lc * 8) * 2,
                 A + (size_t)row * KTOT + k0 + lc * 8);
        }
#pragma unroll
        for (int q0 = 0; q0 < 2; q0++) {
            int r = lr + q0 * 64;
            cp16(bBase + (uint32_t)(buf * TILEW + r * STRIDE + lc * 8) * 2,
                 B + (size_t)(col0 + r) * KTOT + k0 + lc * 8);
        }
    };

    load_stage(0);
    asm volatile("cp.async.commit_group;");

    for (int s = 0; s < NSTG; s++) {
        if (s + 1 < NSTG) {
            load_stage(s + 1);
            asm volatile("cp.async.commit_group;");
            asm volatile("cp.async.wait_group 1;");
        } else {
            asm volatile("cp.async.wait_group 0;");
        }
        __syncthreads();

        int buf = s & 1;
#pragma unroll
        for (int kk = 0; kk < 32; kk += 16) {
            uint32_t a[2][4], b[4][4];
#pragma unroll
            for (int mt = 0; mt < 2; mt++) {
                uint32_t addr = aBase +
                    (uint32_t)(buf * TILEW + (wm + mt * 16 + (lane & 15)) * STRIDE +
                               kk + (lane >> 4) * 8) * 2;
                ldsm_x4(a[mt][0], a[mt][1], a[mt][2], a[mt][3], addr);
            }
#pragma unroll
            for (int nb = 0; nb < 4; nb++) {
                uint32_t addr = bBase +
                    (uint32_t)(buf * TILEW + (wn + nb * 16 + (lane & 15)) * STRIDE +
                               kk + (lane >> 4) * 8) * 2;
                ldsm_x4(b[nb][0], b[nb][1], b[nb][2], b[nb][3], addr);
            }
#pragma unroll
            for (int mt = 0; mt < 2; mt++)
#pragma unroll
                for (int nt = 0; nt < 8; nt++) {
                    int nb = nt >> 1, sel = nt & 1;
                    uint32_t b0 = sel ? b[nb][1] : b[nb][0];
                    uint32_t b1 = sel ? b[nb][3] : b[nb][2];
                    mma16816(acc[mt][nt], a[mt], b0, b1);
                }
        }
        __syncthreads();
    }

    const int r = lane >> 2, c2 = (lane & 3) * 2;
#pragma unroll
    for (int nt = 0; nt < 8; nt++) {
        int j = col0 + wn + nt * 8 + c2;
        float s0 = gg[j] * rsqrtf(vv[j] + 1e-5f);
        float t0 = (bb[j] - mm[j]) * s0 + btv[j];
        float s1 = gg[j + 1] * rsqrtf(vv[j + 1] + 1e-5f);
        float t1 = (bb[j + 1] - mm[j + 1]) * s1 + btv[j + 1];
#pragma unroll
        for (int mt = 0; mt < 2; mt++)
#pragma unroll
            for (int h = 0; h < 2; h++) {
                int row = row0 + wm + mt * 16 + r + h * 8;
                if (row >= NN) continue;
                float z0 = acc[mt][nt][h * 2 + 0] * s0 + t0;
                float z1 = acc[mt][nt][h * 2 + 1] * s1 + t1;
                if (WHICH == 0 || RELU) { z0 = fmaxf(z0, 0.f); z1 = fmaxf(z1, 0.f); }
                if (WHICH == 0) {
                    __nv_bfloat16 h0 = __float2bfloat16(z0), h1 = __float2bfloat16(z1);
                    __nv_bfloat162 hp, lp;
                    hp.x = h0; hp.y = h1;
                    lp.x = __float2bfloat16(z0 - __bfloat162float(h0));
                    lp.y = __float2bfloat16(z1 - __bfloat162float(h1));
                    __nv_bfloat16* base = &g_A2[(size_t)row * 768 + j];
                    *(__nv_bfloat162*)(base + 0)   = hp;
                    *(__nv_bfloat162*)(base + 256) = lp;
                    *(__nv_bfloat162*)(base + 512) = hp;
                } else {
                    *(float2*)&g_x[(size_t)row * D + j] = make_float2(z0, z1);
                }
            }
    }
}

// ---------------- global mean pool ----------------
__global__ void pool_kernel(const int* __restrict__ batch) {
    int n = blockIdx.x * (blockDim.x >> 5) + (threadIdx.x >> 5);
    int lane = threadIdx.x & 31;
    if (n >= NN) return;
    int g = batch[n];
    float4 v = *(const float4*)&g_x[n * D + lane * 4];
    red_add_v4(&g_pool[g * D + lane * 4], v.x, v.y, v.z, v.w);
    if (lane == 0) atomicAdd(&g_cnt[g], 1.0f);
}

// ---------------- prediction head ----------------
__global__ void head_kernel(const float* __restrict__ Wp, const float* __restrict__ bp,
                            float* __restrict__ out) {
    int id = blockIdx.x * blockDim.x + threadIdx.x;
    if (id >= NG * NT) return;
    int g = id / NT, t = id % NT;
    float inv = 1.f / fmaxf(g_cnt[g], 1.f);
    float acc = bp[t];
#pragma unroll 8
    for (int d = 0; d < D; d++)
        acc = fmaf(g_pool[g * D + d] * inv, Wp[d * NT + t], acc);
    out[id] = acc;
}

// ---------------- launch ----------------
extern "C" void kernel_launch(void* const* d_in, const int* in_sizes, int n_in,
                              void* d_out, int out_size) {
    const int*   x_atom  = (const int*)d_in[0];
    const int*   ei      = (const int*)d_in[1];
    const int*   ea      = (const int*)d_in[2];
    const int*   batch   = (const int*)d_in[3];
    const float* atom_emb= (const float*)d_in[4];
    const float* bond_emb= (const float*)d_in[5];
    const float* eps     = (const float*)d_in[6];
    const float* W1      = (const float*)d_in[7];
    const float* b1      = (const float*)d_in[8];
    const float* g1      = (const float*)d_in[9];
    const float* bt1     = (const float*)d_in[10];
    const float* m1      = (const float*)d_in[11];
    const float* v1      = (const float*)d_in[12];
    const float* W2      = (const float*)d_in[13];
    const float* b2      = (const float*)d_in[14];
    const float* gO      = (const float*)d_in[15];
    const float* btO     = (const float*)d_in[16];
    const float* mO      = (const float*)d_in[17];
    const float* vO      = (const float*)d_in[18];
    const float* Wp      = (const float*)d_in[19];
    const float* bp      = (const float*)d_in[20];
    float* out = (float*)d_out;

    // one-time per replay: weight splits + CSR build + atom encode
    prep_w_kernel<<<(NL * 196608 + 255) / 256, 256>>>(W1, W2);
    zero_deg_kernel<<<(NN + 255) / 256, 256>>>();
    hist_kernel<<<(NE + 255) / 256, 256>>>(ei);
    scan_kernel<<<1, 1024>>>();
    permute_kernel<<<(NE + 255) / 256, 256>>>(ei, ea);
    atom_encode_kernel<<<NN / 8, 256>>>(x_atom, atom_emb);

    const int MT = (NN + 127) / 128;  // 313 row tiles

    for (int i = 0; i < NL; i++) {
        // fused: aggregation + (1+eps)x+agg + bf16 split
        agg_a1_kernel<<<NN / 8, 256>>>(eps + i, bond_emb + i * 3 * 8 * D);

        // GEMM1: [NN x 384] x [384 x 256] -> hidden (relu) -> g_A2 splits
        mma_gemm_kernel<0, true><<<dim3(2, MT), 256>>>(
            i * 98304,
            b1 + i * 256, g1 + i * 256, bt1 + i * 256, m1 + i * 256, v1 + i * 256);

        // GEMM2: [NN x 768] x [768 x 128] -> outer BN (+relu except last) -> g_x
        if (i < NL - 1)
            mma_gemm_kernel<1, true><<<dim3(1, MT), 256>>>(
                i * 98304,
                b2 + i * 128, gO + i * 128, btO + i * 128, mO + i * 128, vO + i * 128);
        else
            mma_gemm_kernel<1, false><<<dim3(1, MT), 256>>>(
                i * 98304,
                b2 + i * 128, gO + i * 128, btO + i * 128, mO + i * 128, vO + i * 128);
    }

    zero_pool_kernel<<<(NG * D + 255) / 256, 256>>>();
    pool_kernel<<<NN / 8, 256>>>(batch);
    head_kernel<<<(NG * NT + 255) / 256, 256>>>(Wp, bp, out);
}

// round 12
// speedup vs baseline: 1.9249x; 1.1441x over previous
#include <cuda_runtime.h>
#include <cuda_bf16.h>
#include <cstdint>

#define NN 40000
#define NE 640000
#define NG 2048
#define D  128
#define NT 10
#define NL 5
#define SCAN_BLOCKS 40   // ceil(NN / 1024)

// ---------------- scratch (device globals: allocation-free) ----------------
__device__ float g_x[NN * D];                 // current node features (fp32)
__device__ __align__(16) __nv_bfloat16 g_A1[NN * 256];          // [hi|lo] of (1+eps)x+agg
__device__ __align__(16) __nv_bfloat16 g_A2[(size_t)NN * 512];  // [hi|lo] of MLP hidden
__device__ __align__(16) __nv_bfloat16 g_W1T[NL * 256 * 384];   // [n][k'] per layer: hi,hi,lo
__device__ __align__(16) __nv_bfloat16 g_W2T[NL * 128 * 768];
__device__ float g_pool[NG * D];
__device__ float g_cnt[NG];
// CSR scratch (built once per replay)
__device__ int g_deg[NN];
__device__ int g_pos[NN];
__device__ int g_rowptr[NN + 1];
__device__ int g_csr_src[NE];
__device__ int g_csr_code[NE];   // packed bond attrs: a0 | a1<<3 | a2<<6
__device__ int g_blocksum[SCAN_BLOCKS];
__device__ int g_blockoff[SCAN_BLOCKS];

__device__ __forceinline__ void red_add_v4(float* p, float a, float b, float c, float d) {
    asm volatile("red.global.add.v4.f32 [%0], {%1,%2,%3,%4};"
                 :: "l"(p), "f"(a), "f"(b), "f"(c), "f"(d) : "memory");
}
__device__ __forceinline__ void cp16(uint32_t s, const void* g) {
    asm volatile("cp.async.cg.shared.global [%0], [%1], 16;" :: "r"(s), "l"(g));
}
__device__ __forceinline__ void ldsm_x4(uint32_t& r0, uint32_t& r1, uint32_t& r2, uint32_t& r3,
                                        uint32_t addr) {
    asm volatile("ldmatrix.sync.aligned.m8n8.x4.shared.b16 {%0,%1,%2,%3}, [%4];"
                 : "=r"(r0), "=r"(r1), "=r"(r2), "=r"(r3) : "r"(addr));
}
__device__ __forceinline__ void mma16816(float* d, const uint32_t* a, uint32_t b0, uint32_t b1) {
    asm volatile("mma.sync.aligned.m16n8k16.row.col.f32.bf16.bf16.f32 "
                 "{%0,%1,%2,%3},{%4,%5,%6,%7},{%8,%9},{%0,%1,%2,%3};"
                 : "+f"(d[0]), "+f"(d[1]), "+f"(d[2]), "+f"(d[3])
                 : "r"(a[0]), "r"(a[1]), "r"(a[2]), "r"(a[3]), "r"(b0), "r"(b1));
}

// ---------------- CSR build (once per replay) ----------------
__global__ void zero_deg_kernel() {
    int i = blockIdx.x * blockDim.x + threadIdx.x;
    if (i < NN) { g_deg[i] = 0; g_pos[i] = 0; }
}
__global__ void hist_kernel(const int* __restrict__ ei) {
    int e = blockIdx.x * blockDim.x + threadIdx.x;
    if (e < NE) atomicAdd(&g_deg[ei[NE + e]], 1);
}
// step 1: per-block (1024-wide) inclusive scan via warp shuffles
__global__ void scan_block_kernel() {
    __shared__ int warpsum[32];
    int tid = threadIdx.x;
    int gid = blockIdx.x * 1024 + tid;
    int lane = tid & 31, wid = tid >> 5;
    int x = (gid < NN) ? g_deg[gid] : 0;
#pragma unroll
    for (int o = 1; o < 32; o <<= 1) {
        int y = __shfl_up_sync(0xffffffffu, x, o);
        if (lane >= o) x += y;
    }
    if (lane == 31) warpsum[wid] = x;
    __syncthreads();
    if (wid == 0) {
        int s = warpsum[lane];
#pragma unroll
        for (int o = 1; o < 32; o <<= 1) {
            int y = __shfl_up_sync(0xffffffffu, s, o);
            if (lane >= o) s += y;
        }
        warpsum[lane] = s;
    }
    __syncthreads();
    int total = x + (wid > 0 ? warpsum[wid - 1] : 0);
    if (gid < NN) g_rowptr[gid + 1] = total;
    if (tid == 1023) g_blocksum[blockIdx.x] = total;
}
// step 2: tiny sequential scan of block sums (40 entries)
__global__ void scan_top_kernel() {
    if (threadIdx.x == 0) {
        int run = 0;
        for (int b = 0; b < SCAN_BLOCKS; b++) {
            g_blockoff[b] = run;
            run += g_blocksum[b];
        }
        g_rowptr[0] = 0;
    }
}
// step 3: add block offsets
__global__ void scan_add_kernel() {
    int gid = blockIdx.x * blockDim.x + threadIdx.x;
    if (gid < NN) {
        int b = gid >> 10;
        if (b > 0) g_rowptr[gid + 1] += g_blockoff[b];
    }
}
__global__ void permute_kernel(const int* __restrict__ ei, const int* __restrict__ ea) {
    int e = blockIdx.x * blockDim.x + threadIdx.x;
    if (e >= NE) return;
    int dst = ei[NE + e];
    int p = g_rowptr[dst] + atomicAdd(&g_pos[dst], 1);
    g_csr_src[p] = ei[e];
    g_csr_code[p] = ea[e * 3 + 0] | (ea[e * 3 + 1] << 3) | (ea[e * 3 + 2] << 6);
}

// ---------------- zero pool ----------------
__global__ void zero_pool_kernel() {
    int i = blockIdx.x * blockDim.x + threadIdx.x;
    if (i < NG * D) g_pool[i] = 0.f;
    if (i < NG) g_cnt[i] = 0.f;
}

// ---------------- atom encoder ----------------
__global__ void atom_encode_kernel(const int* __restrict__ x_atom,
                                   const float* __restrict__ atom_emb) {
    int n = blockIdx.x * (blockDim.x >> 5) + (threadIdx.x >> 5);
    int lane = threadIdx.x & 31;
    if (n >= NN) return;
    float4 acc = make_float4(0.f, 0.f, 0.f, 0.f);
#pragma unroll
    for (int f = 0; f < 9; f++) {
        int idx = __ldg(&x_atom[n * 9 + f]);
        float4 v = *(const float4*)&atom_emb[(f * 64 + idx) * D + lane * 4];
        acc.x += v.x; acc.y += v.y; acc.z += v.z; acc.w += v.w;
    }
    *(float4*)&g_x[n * D + lane * 4] = acc;
}

// ---------------- fused aggregation + A1-split kernel ----------------
__global__ __launch_bounds__(256)
void agg_a1_kernel(const float* __restrict__ epsp, const float* __restrict__ bond) {
    __shared__ float sbond[3 * 8 * D];   // 12 KB
    int tid = threadIdx.x;
    for (int i = tid; i < 3 * 8 * D / 4; i += 256)
        ((float4*)sbond)[i] = ((const float4*)bond)[i];
    __syncthreads();

    int n = blockIdx.x * 8 + (tid >> 5);
    int lane = tid & 31;
    if (n >= NN) return;
    int off = lane * 4;

    float4 acc = make_float4(0.f, 0.f, 0.f, 0.f);
    int e = g_rowptr[n], end = g_rowptr[n + 1];

    auto accum = [&](int src, int code) {
        float4 xv = *(const float4*)&g_x[src * D + off];
        float4 b0 = *(const float4*)&sbond[(code & 7) * D + off];
        float4 b1 = *(const float4*)&sbond[1024 + ((code >> 3) & 7) * D + off];
        float4 b2 = *(const float4*)&sbond[2048 + ((code >> 6) & 7) * D + off];
        acc.x += fmaxf(xv.x + b0.x + b1.x + b2.x, 0.f);
        acc.y += fmaxf(xv.y + b0.y + b1.y + b2.y, 0.f);
        acc.z += fmaxf(xv.z + b0.z + b1.z + b2.z, 0.f);
        acc.w += fmaxf(xv.w + b0.w + b1.w + b2.w, 0.f);
    };

    for (; e + 3 < end; e += 4) {
        int s0 = g_csr_src[e],     c0 = g_csr_code[e];
        int s1 = g_csr_src[e + 1], c1 = g_csr_code[e + 1];
        int s2 = g_csr_src[e + 2], c2 = g_csr_code[e + 2];
        int s3 = g_csr_src[e + 3], c3 = g_csr_code[e + 3];
        accum(s0, c0); accum(s1, c1); accum(s2, c2); accum(s3, c3);
    }
    for (; e < end; e++) accum(g_csr_src[e], g_csr_code[e]);

    float alpha = 1.f + *epsp;
    float4 xn = *(const float4*)&g_x[n * D + off];
    float a0 = alpha * xn.x + acc.x, a1 = alpha * xn.y + acc.y;
    float a2 = alpha * xn.z + acc.z, a3 = alpha * xn.w + acc.w;
    __nv_bfloat16 h0 = __float2bfloat16(a0), h1 = __float2bfloat16(a1);
    __nv_bfloat16 h2 = __float2bfloat16(a2), h3 = __float2bfloat16(a3);
    __nv_bfloat162 hp0, hp1, lp0, lp1;
    hp0.x = h0; hp0.y = h1; hp1.x = h2; hp1.y = h3;
    lp0.x = __float2bfloat16(a0 - __bfloat162float(h0));
    lp0.y = __float2bfloat16(a1 - __bfloat162float(h1));
    lp1.x = __float2bfloat16(a2 - __bfloat162float(h2));
    lp1.y = __float2bfloat16(a3 - __bfloat162float(h3));
    __nv_bfloat16* base = &g_A1[n * 256 + off];
    *(__nv_bfloat162*)(base + 0)   = hp0; *(__nv_bfloat162*)(base + 2)   = hp1;
    *(__nv_bfloat162*)(base + 128) = lp0; *(__nv_bfloat162*)(base + 130) = lp1;
}

// ---------------- weight split prep ----------------
__global__ void prep_w_kernel(const float* __restrict__ W1, const float* __restrict__ W2) {
    int idx = blockIdx.x * blockDim.x + threadIdx.x;
    if (idx >= NL * 196608) return;
    int layer = idx / 196608, rem = idx % 196608;
    if (rem < 98304) {  // W1T: n in [0,256), kp in [0,384)
        int n = rem / 384, kp = rem % 384;
        int kb = kp >> 7, k = kp & 127;
        float w = W1[layer * 32768 + k * 256 + n];
        __nv_bfloat16 h = __float2bfloat16(w);
        g_W1T[layer * 98304 + rem] =
            (kb < 2) ? h : __float2bfloat16(w - __bfloat162float(h));
    } else {            // W2T: n in [0,128), kp in [0,768)
        int r2 = rem - 98304;
        int n = r2 / 768, kp = r2 % 768;
        int kb = kp >> 8, k = kp & 255;
        float w = W2[layer * 32768 + k * 128 + n];
        __nv_bfloat16 h = __float2bfloat16(w);
        g_W2T[layer * 98304 + r2] =
            (kb < 2) ? h : __float2bfloat16(w - __bfloat162float(h));
    }
}

// ---------------- tensor-core GEMM + BN epilogue ----------------
// A stored deduped [hi|lo] (ASTRIDE cols); K-stages map block {0,1,2}->{hi,lo,hi}.
template<int WHICH, bool RELU>
__global__ __launch_bounds__(256)
void mma_gemm_kernel(int wOff,
                     const float* __restrict__ bb, const float* __restrict__ gg,
                     const float* __restrict__ btv, const float* __restrict__ mm,
                     const float* __restrict__ vv) {
    constexpr int KTOT = (WHICH == 0) ? 384 : 768;   // W layout K (hi,hi,lo)
    constexpr int DH   = (WHICH == 0) ? 128 : 256;   // one A block
    constexpr int ASTRIDE = 2 * DH;                  // A row stride [hi|lo]
    constexpr int STRIDE = 40;
    constexpr int TILEW  = 128 * STRIDE;
    __shared__ __align__(16) __nv_bfloat16 sA[2][TILEW];
    __shared__ __align__(16) __nv_bfloat16 sB[2][TILEW];

    const __nv_bfloat16* __restrict__ A = (WHICH == 0) ? g_A1 : g_A2;
    const __nv_bfloat16* __restrict__ B = ((WHICH == 0) ? g_W1T : g_W2T) + wOff;

    const int tid = threadIdx.x, wid = tid >> 5, lane = tid & 31;
    const int wm = (wid & 3) * 32, wn = (wid >> 2) * 64;
    const int row0 = blockIdx.y * 128, col0 = blockIdx.x * 128;

    uint32_t aBase = (uint32_t)__cvta_generic_to_shared(&sA[0][0]);
    uint32_t bBase = (uint32_t)__cvta_generic_to_shared(&sB[0][0]);

    float acc[2][8][4];
#pragma unroll
    for (int i = 0; i < 2; i++)
#pragma unroll
        for (int j = 0; j < 8; j++)
#pragma unroll
            for (int k = 0; k < 4; k++) acc[i][j][k] = 0.f;

    const int NSTG = KTOT / 32;
    const int SPB  = NSTG / 3;           // stages per block
    const int lr = tid >> 2, lc = tid & 3;

    auto load_stage = [&](int s) {
        int buf = s & 1, k0 = s * 32;
        int blk = s / SPB, si = s - blk * SPB;
        int k0A = si * 32 + (blk == 1 ? DH : 0);   // block 0,2 -> hi; block 1 -> lo
#pragma unroll
        for (int q0 = 0; q0 < 2; q0++) {
            int r = lr + q0 * 64;
            int row = row0 + r; if (row >= NN) row = NN - 1;
            cp16(aBase + (uint32_t)(buf * TILEW + r * STRIDE + lc * 8) * 2,
                 A + (size_t)row * ASTRIDE + k0A + lc * 8);
        }
#pragma unroll
        for (int q0 = 0; q0 < 2; q0++) {
            int r = lr + q0 * 64;
            cp16(bBase + (uint32_t)(buf * TILEW + r * STRIDE + lc * 8) * 2,
                 B + (size_t)(col0 + r) * KTOT + k0 + lc * 8);
        }
    };

    load_stage(0);
    asm volatile("cp.async.commit_group;");

    for (int s = 0; s < NSTG; s++) {
        if (s + 1 < NSTG) {
            load_stage(s + 1);
            asm volatile("cp.async.commit_group;");
            asm volatile("cp.async.wait_group 1;");
        } else {
            asm volatile("cp.async.wait_group 0;");
        }
        __syncthreads();

        int buf = s & 1;
#pragma unroll
        for (int kk = 0; kk < 32; kk += 16) {
            uint32_t a[2][4], b[4][4];
#pragma unroll
            for (int mt = 0; mt < 2; mt++) {
                uint32_t addr = aBase +
                    (uint32_t)(buf * TILEW + (wm + mt * 16 + (lane & 15)) * STRIDE +
                               kk + (lane >> 4) * 8) * 2;
                ldsm_x4(a[mt][0], a[mt][1], a[mt][2], a[mt][3], addr);
            }
#pragma unroll
            for (int nb = 0; nb < 4; nb++) {
                uint32_t addr = bBase +
                    (uint32_t)(buf * TILEW + (wn + nb * 16 + (lane & 15)) * STRIDE +
                               kk + (lane >> 4) * 8) * 2;
                ldsm_x4(b[nb][0], b[nb][1], b[nb][2], b[nb][3], addr);
            }
#pragma unroll
            for (int mt = 0; mt < 2; mt++)
#pragma unroll
                for (int nt = 0; nt < 8; nt++) {
                    int nb = nt >> 1, sel = nt & 1;
                    uint32_t b0 = sel ? b[nb][1] : b[nb][0];
                    uint32_t b1 = sel ? b[nb][3] : b[nb][2];
                    mma16816(acc[mt][nt], a[mt], b0, b1);
                }
        }
        __syncthreads();
    }

    const int r = lane >> 2, c2 = (lane & 3) * 2;
#pragma unroll
    for (int nt = 0; nt < 8; nt++) {
        int j = col0 + wn + nt * 8 + c2;
        float s0 = gg[j] * rsqrtf(vv[j] + 1e-5f);
        float t0 = (bb[j] - mm[j]) * s0 + btv[j];
        float s1 = gg[j + 1] * rsqrtf(vv[j + 1] + 1e-5f);
        float t1 = (bb[j + 1] - mm[j + 1]) * s1 + btv[j + 1];
#pragma unroll
        for (int mt = 0; mt < 2; mt++)
#pragma unroll
            for (int h = 0; h < 2; h++) {
                int row = row0 + wm + mt * 16 + r + h * 8;
                if (row >= NN) continue;
                float z0 = acc[mt][nt][h * 2 + 0] * s0 + t0;
                float z1 = acc[mt][nt][h * 2 + 1] * s1 + t1;
                if (WHICH == 0 || RELU) { z0 = fmaxf(z0, 0.f); z1 = fmaxf(z1, 0.f); }
                if (WHICH == 0) {
                    __nv_bfloat16 h0 = __float2bfloat16(z0), h1 = __float2bfloat16(z1);
                    __nv_bfloat162 hp, lp;
                    hp.x = h0; hp.y = h1;
                    lp.x = __float2bfloat16(z0 - __bfloat162float(h0));
                    lp.y = __float2bfloat16(z1 - __bfloat162float(h1));
                    __nv_bfloat16* base = &g_A2[(size_t)row * 512 + j];
                    *(__nv_bfloat162*)(base + 0)   = hp;
                    *(__nv_bfloat162*)(base + 256) = lp;
                } else {
                    *(float2*)&g_x[(size_t)row * D + j] = make_float2(z0, z1);
                }
            }
    }
}

// ---------------- global mean pool ----------------
__global__ void pool_kernel(const int* __restrict__ batch) {
    int n = blockIdx.x * (blockDim.x >> 5) + (threadIdx.x >> 5);
    int lane = threadIdx.x & 31;
    if (n >= NN) return;
    int g = batch[n];
    float4 v = *(const float4*)&g_x[n * D + lane * 4];
    red_add_v4(&g_pool[g * D + lane * 4], v.x, v.y, v.z, v.w);
    if (lane == 0) atomicAdd(&g_cnt[g], 1.0f);
}

// ---------------- prediction head ----------------
__global__ void head_kernel(const float* __restrict__ Wp, const float* __restrict__ bp,
                            float* __restrict__ out) {
    int id = blockIdx.x * blockDim.x + threadIdx.x;
    if (id >= NG * NT) return;
    int g = id / NT, t = id % NT;
    float inv = 1.f / fmaxf(g_cnt[g], 1.f);
    float acc = bp[t];
#pragma unroll 8
    for (int d = 0; d < D; d++)
        acc = fmaf(g_pool[g * D + d] * inv, Wp[d * NT + t], acc);
    out[id] = acc;
}

// ---------------- launch ----------------
extern "C" void kernel_launch(void* const* d_in, const int* in_sizes, int n_in,
                              void* d_out, int out_size) {
    const int*   x_atom  = (const int*)d_in[0];
    const int*   ei      = (const int*)d_in[1];
    const int*   ea      = (const int*)d_in[2];
    const int*   batch   = (const int*)d_in[3];
    const float* atom_emb= (const float*)d_in[4];
    const float* bond_emb= (const float*)d_in[5];
    const float* eps     = (const float*)d_in[6];
    const float* W1      = (const float*)d_in[7];
    const float* b1      = (const float*)d_in[8];
    const float* g1      = (const float*)d_in[9];
    const float* bt1     = (const float*)d_in[10];
    const float* m1      = (const float*)d_in[11];
    const float* v1      = (const float*)d_in[12];
    const float* W2      = (const float*)d_in[13];
    const float* b2      = (const float*)d_in[14];
    const float* gO      = (const float*)d_in[15];
    const float* btO     = (const float*)d_in[16];
    const float* mO      = (const float*)d_in[17];
    const float* vO      = (const float*)d_in[18];
    const float* Wp      = (const float*)d_in[19];
    const float* bp      = (const float*)d_in[20];
    float* out = (float*)d_out;

    // one-time per replay: weight splits + CSR build + atom encode
    prep_w_kernel<<<(NL * 196608 + 255) / 256, 256>>>(W1, W2);
    zero_deg_kernel<<<(NN + 255) / 256, 256>>>();
    hist_kernel<<<(NE + 255) / 256, 256>>>(ei);
    scan_block_kernel<<<SCAN_BLOCKS, 1024>>>();
    scan_top_kernel<<<1, 32>>>();
    scan_add_kernel<<<(NN + 255) / 256, 256>>>();
    permute_kernel<<<(NE + 255) / 256, 256>>>(ei, ea);
    atom_encode_kernel<<<NN / 8, 256>>>(x_atom, atom_emb);

    const int MT = (NN + 127) / 128;  // 313 row tiles

    for (int i = 0; i < NL; i++) {
        agg_a1_kernel<<<NN / 8, 256>>>(eps + i, bond_emb + i * 3 * 8 * D);

        mma_gemm_kernel<0, true><<<dim3(2, MT), 256>>>(
            i * 98304,
            b1 + i * 256, g1 + i * 256, bt1 + i * 256, m1 + i * 256, v1 + i * 256);

        if (i < NL - 1)
            mma_gemm_kernel<1, true><<<dim3(1, MT), 256>>>(
                i * 98304,
                b2 + i * 128, gO + i * 128, btO + i * 128, mO + i * 128, vO + i * 128);
        else
            mma_gemm_kernel<1, false><<<dim3(1, MT), 256>>>(
                i * 98304,
                b2 + i * 128, gO + i * 128, btO + i * 128, mO + i * 128, vO + i * 128);
    }

    zero_pool_kernel<<<(NG * D + 255) / 256, 256>>>();
    pool_kernel<<<NN / 8, 256>>>(batch);
    head_kernel<<<(NG * NT + 255) / 256, 256>>>(Wp, bp, out);
}